// round 5
// baseline (speedup 1.0000x reference)
#include <cuda_runtime.h>
#include <cuda_bf16.h>
#include <cfloat>

#define NN  50000
#define EE  1600000
#define FIN 8
#define HIDD 1000
#define RR  100

// ---------------- scratch (no allocations allowed) ----------------
__device__ float g_sum[NN];        // segment_sum of dot(X[src], lin_l_w)
__device__ int   g_cnt[NN];        // in-degree
__device__ float g_max[NN * FIN];  // per-feature segment max
__device__ float g_p[NN];          // dot(X[i], lin_l_w) precomputed per node
__device__ float g_x[NN];          // embedding (MLP input)
__device__ float g_h0[HIDD];
__device__ float g_h1[HIDD];
__device__ int   g_idx64;          // 1 if edge_index is int64, 0 if int32

// ---------------- helpers ----------------
__device__ __forceinline__ void atomicMaxF(float* addr, float val) {
    // standard signed/unsigned split trick; init value is -inf (0xFF800000)
    if (val >= 0.0f)
        atomicMax((int*)addr, __float_as_int(val));
    else
        atomicMin((unsigned int*)addr, __float_as_uint(val));
}

__device__ __forceinline__ float dot8(float4 a, float4 b, const float* __restrict__ w) {
    return a.x * w[0] + a.y * w[1] + a.z * w[2] + a.w * w[3]
         + b.x * w[4] + b.y * w[5] + b.z * w[6] + b.w * w[7];
}

// ---------------- kernels ----------------

// Detect whether edge_index arrived as int64 or int32.
// int32 data reinterpreted as int64 packs two random indices into one word ->
// values >= NN with overwhelming probability across 16 samples.
__global__ void detect_kernel(const long long* __restrict__ ei) {
    if (blockIdx.x == 0 && threadIdx.x == 0) {
        int ok = 1;
        #pragma unroll
        for (int i = 0; i < 16; i++) {
            long long v = ei[i];
            if (v < 0 || v >= (long long)NN) ok = 0;
        }
        g_idx64 = ok;
    }
}

// Zero sums/counts, set maxes to -inf, precompute p[i] = dot(X[i], lin_l_w).
__global__ void init_kernel(const float* __restrict__ X, const float* __restrict__ wl) {
    int i = blockIdx.x * blockDim.x + threadIdx.x;
    if (i < NN * FIN) g_max[i] = -FLT_MAX;  // any real msg beats this; masked by cnt anyway
    if (i < NN) {
        g_sum[i] = 0.0f;
        g_cnt[i] = 0;
        const float4* x4 = (const float4*)(X + (size_t)i * FIN);
        float4 a = x4[0], b = x4[1];
        g_p[i] = dot8(a, b, wl);
    }
}

__global__ void edge_kernel(const void* __restrict__ eiv, const float* __restrict__ X) {
    int e = blockIdx.x * blockDim.x + threadIdx.x;
    if (e >= EE) return;
    int s, d;
    if (g_idx64) {
        const long long* ei = (const long long*)eiv;
        s = (int)ei[e];
        d = (int)ei[EE + e];
    } else {
        const int* ei = (const int*)eiv;
        s = ei[e];
        d = ei[EE + e];
    }
    atomicAdd(&g_sum[d], g_p[s]);
    atomicAdd(&g_cnt[d], 1);
    const float4* x4 = (const float4*)(X + (size_t)s * FIN);
    float4 a = x4[0], b = x4[1];
    float* m = &g_max[(size_t)d * FIN];
    atomicMaxF(m + 0, a.x);
    atomicMaxF(m + 1, a.y);
    atomicMaxF(m + 2, a.z);
    atomicMaxF(m + 3, a.w);
    atomicMaxF(m + 4, b.x);
    atomicMaxF(m + 5, b.y);
    atomicMaxF(m + 6, b.z);
    atomicMaxF(m + 7, b.w);
}

__global__ void node_kernel(const float* __restrict__ X,
                            const float* __restrict__ lin_l_b,
                            const float* __restrict__ lin_r_w,
                            const float* __restrict__ lin_l1_w,
                            const float* __restrict__ lin_l1_b,
                            const float* __restrict__ lin_r1_w,
                            float* __restrict__ out) {
    int i = blockIdx.x * blockDim.x + threadIdx.x;
    if (i >= NN) return;
    float cnt = (float)g_cnt[i];
    float mean = g_sum[i] / fmaxf(cnt, 1.0f);  // agg_mean . lin_l_w
    const float4* x4 = (const float4*)(X + (size_t)i * FIN);
    float4 a = x4[0], b = x4[1];
    float xr  = dot8(a, b, lin_r_w);
    float xr1 = dot8(a, b, lin_r1_w);
    float mx = 0.0f;
    if (cnt > 0.0f) {
        const float* m = &g_max[(size_t)i * FIN];
        mx = m[0] * lin_l1_w[0] + m[1] * lin_l1_w[1] + m[2] * lin_l1_w[2] + m[3] * lin_l1_w[3]
           + m[4] * lin_l1_w[4] + m[5] * lin_l1_w[5] + m[6] * lin_l1_w[6] + m[7] * lin_l1_w[7];
    }
    float hm = fmaxf(mean + lin_l_b[0] + xr, 0.0f);
    float hx = fmaxf(mx + lin_l1_b[0] + xr1, 0.0f);
    float v = hm + hx;
    out[i] = v;   // X_embedding slot of output
    g_x[i] = v;   // MLP input
}

// y[row] = relu(W[row,:] . x + b[row]); one block per row, float4 streaming.
__global__ void gemv_relu_kernel(const float* __restrict__ W,
                                 const float* __restrict__ b,
                                 const float* __restrict__ x,
                                 float* __restrict__ y,
                                 int in4) {  // in_dim / 4
    int row = blockIdx.x;
    const float4* w4 = (const float4*)(W + (size_t)row * (size_t)in4 * 4);
    const float4* x4 = (const float4*)x;
    float acc = 0.0f;
    for (int c = threadIdx.x; c < in4; c += blockDim.x) {
        float4 w = w4[c];
        float4 v = x4[c];
        acc += w.x * v.x + w.y * v.y + w.z * v.z + w.w * v.w;
    }
    // block reduce
    __shared__ float sh[32];
    #pragma unroll
    for (int o = 16; o; o >>= 1) acc += __shfl_down_sync(0xffffffffu, acc, o);
    int lane = threadIdx.x & 31, wid = threadIdx.x >> 5;
    if (lane == 0) sh[wid] = acc;
    __syncthreads();
    if (wid == 0) {
        int nw = blockDim.x >> 5;
        acc = (lane < nw) ? sh[lane] : 0.0f;
        #pragma unroll
        for (int o = 16; o; o >>= 1) acc += __shfl_down_sync(0xffffffffu, acc, o);
        if (lane == 0) y[row] = fmaxf(acc + b[row], 0.0f);
    }
}

// ---------------- launch ----------------
extern "C" void kernel_launch(void* const* d_in, const int* in_sizes, int n_in,
                              void* d_out, int out_size) {
    const float* X        = (const float*)d_in[0];
    const void*  ei       = d_in[1];               // int64 or int32, detected on device
    const float* lin_l_w  = (const float*)d_in[2];
    const float* lin_l_b  = (const float*)d_in[3];
    const float* lin_r_w  = (const float*)d_in[4];
    const float* lin_l1_w = (const float*)d_in[5];
    const float* lin_l1_b = (const float*)d_in[6];
    const float* lin_r1_w = (const float*)d_in[7];
    const float* W0       = (const float*)d_in[8];
    const float* b0       = (const float*)d_in[9];
    const float* W1       = (const float*)d_in[10];
    const float* b1       = (const float*)d_in[11];
    const float* W2       = (const float*)d_in[12];
    const float* b2       = (const float*)d_in[13];
    float* out = (float*)d_out;  // [NN + RR] = embedding ++ mlp_out

    detect_kernel<<<1, 32>>>((const long long*)ei);
    init_kernel<<<(NN * FIN + 255) / 256, 256>>>(X, lin_l_w);
    edge_kernel<<<(EE + 255) / 256, 256>>>(ei, X);
    node_kernel<<<(NN + 255) / 256, 256>>>(X, lin_l_b, lin_r_w,
                                           lin_l1_w, lin_l1_b, lin_r1_w, out);

    float* g_x_ptr;  float* g_h0_ptr;  float* g_h1_ptr;
    cudaGetSymbolAddress((void**)&g_x_ptr,  g_x);
    cudaGetSymbolAddress((void**)&g_h0_ptr, g_h0);
    cudaGetSymbolAddress((void**)&g_h1_ptr, g_h1);

    gemv_relu_kernel<<<HIDD, 256>>>(W0, b0, g_x_ptr,  g_h0_ptr, NN / 4);    // 1000 x 50000
    gemv_relu_kernel<<<HIDD, 256>>>(W1, b1, g_h0_ptr, g_h1_ptr, HIDD / 4);  // 1000 x 1000
    gemv_relu_kernel<<<RR,   256>>>(W2, b2, g_h1_ptr, out + NN, HIDD / 4);  // 100 x 1000
}